// round 3
// baseline (speedup 1.0000x reference)
#include <cuda_runtime.h>

#define BQ 4096
#define NTOK 49
#define EMB 256
#define NHEADS 8
#define HD 32
#define MROWS (BQ*NTOK)   // 200704 = 128*1568

// Scratch (device globals: allocation-free). __align__(16): these are read
// through float4 casts; plain float arrays only guarantee 4-byte alignment.
__device__ __align__(16) float g_q[BQ*NHEADS*NTOK*HD];
__device__ __align__(16) float g_k[BQ*NHEADS*NTOK*HD];
__device__ __align__(16) float g_v[BQ*NHEADS*NTOK*HD];
__device__ __align__(16) float g_att[MROWS*EMB];

// ---------------------------------------------------------------------------
// 128x128x8 fp32 GEMM, C[m][n] = sum_k A[m][k] * W[n][k]  (+bias, epilogue)
// MODE 0: A = x, W = qkv_w, scatter into g_q/g_k/g_v with q-scale
// MODE 1: A = g_att, W = proj_w, write out
// ---------------------------------------------------------------------------
template<int MODE>
__global__ void __launch_bounds__(256, 2)
gemm128(const float* __restrict__ A_in, const float* __restrict__ W,
        const float* __restrict__ bias, float* __restrict__ out)
{
    __shared__ __align__(16) float As[8][128];
    __shared__ __align__(16) float Bs[8][128];

    const float* __restrict__ A = (MODE == 0) ? A_in : (const float*)g_att;

    const int tid = threadIdx.x;
    const int tx  = tid & 15;
    const int ty  = tid >> 4;
    const int m0  = blockIdx.y * 128;
    const int n0b = blockIdx.x * 128;

    // cooperative loads: thread -> (row r, 4 k-values)
    const int r  = tid >> 1;
    const int kc = (tid & 1) * 4;
    const float* Ag = A + (m0  + r) * EMB + kc;
    const float* Wg = W + (n0b + r) * EMB + kc;

    float acc[8][8];
#pragma unroll
    for (int i = 0; i < 8; i++)
#pragma unroll
        for (int j = 0; j < 8; j++) acc[i][j] = 0.f;

    for (int k0 = 0; k0 < EMB; k0 += 8) {
        float4 a  = *(const float4*)(Ag + k0);
        float4 w4 = *(const float4*)(Wg + k0);
        As[kc+0][r] = a.x;  As[kc+1][r] = a.y;  As[kc+2][r] = a.z;  As[kc+3][r] = a.w;
        Bs[kc+0][r] = w4.x; Bs[kc+1][r] = w4.y; Bs[kc+2][r] = w4.z; Bs[kc+3][r] = w4.w;
        __syncthreads();
#pragma unroll
        for (int kk = 0; kk < 8; kk++) {
            const float4 a0 = *(const float4*)&As[kk][ty*8];
            const float4 a1 = *(const float4*)&As[kk][ty*8+4];
            const float4 b0 = *(const float4*)&Bs[kk][tx*8];
            const float4 b1 = *(const float4*)&Bs[kk][tx*8+4];
            const float fa[8] = {a0.x,a0.y,a0.z,a0.w,a1.x,a1.y,a1.z,a1.w};
            const float fb[8] = {b0.x,b0.y,b0.z,b0.w,b1.x,b1.y,b1.z,b1.w};
#pragma unroll
            for (int i = 0; i < 8; i++)
#pragma unroll
                for (int j = 0; j < 8; j++) acc[i][j] += fa[i] * fb[j];
        }
        __syncthreads();
    }

    const int n0 = n0b + tx * 8;
#pragma unroll
    for (int i = 0; i < 8; i++) {
        const int m = m0 + ty * 8 + i;
        if (MODE == 0) {
            // scatter to q/k/v [B, H, 49, 32]; col n0 -> (sel, h, d)
            const int b   = m / NTOK;
            const int nn  = m - b * NTOK;
            const int sel = n0 >> 8;
            const int h   = (n0 >> 5) & 7;
            const int d   = n0 & 31;
            float* dst = (sel == 0 ? g_q : (sel == 1 ? g_k : g_v))
                         + ((b * NHEADS + h) * NTOK + nn) * HD + d;
            const float scl = (sel == 0) ? 0.17677669529663687f : 1.0f; // hd^-0.5
#pragma unroll
            for (int j = 0; j < 8; j++) dst[j] = (acc[i][j] + bias[n0 + j]) * scl;
        } else {
            float* dst = out + m * EMB + n0;
#pragma unroll
            for (int j = 0; j < 8; j++) dst[j] = acc[i][j] + bias[n0 + j];
        }
    }
}

// ---------------------------------------------------------------------------
// Attention: one block per (b,h). q/k/v tiles + logits in smem.
// Thread t (<49) owns query row t: 49 logits, softmax, 49x32 PV.
// ---------------------------------------------------------------------------
__global__ void __launch_bounds__(64)
attn_kernel(const float* __restrict__ mask, const float* __restrict__ bias_table)
{
    // All four arrays are float4-accessed or follow a float4-accessed array:
    // force 16-byte alignment and 16-byte-multiple sizes.
    __shared__ __align__(16) float sk[NTOK * 32];    // 6272 B
    __shared__ __align__(16) float sv[NTOK * 32];    // 6272 B
    __shared__ __align__(16) float sq[NTOK * 33 + 3];// padded stride 33, size mult of 16
    __shared__ __align__(16) float slog[64 * 49];

    const int tid = threadIdx.x;
    const int bh  = blockIdx.x;
    const int b   = bh >> 3;
    const int h   = bh & 7;

    const float* qp = g_q + bh * (NTOK * HD);
    const float* kp = g_k + bh * (NTOK * HD);
    const float* vp = g_v + bh * (NTOK * HD);

    for (int i = tid; i < (NTOK * HD) / 4; i += 64) {   // 392 float4s
        ((float4*)sk)[i] = ((const float4*)kp)[i];
        ((float4*)sv)[i] = ((const float4*)vp)[i];
        float4 q4 = ((const float4*)qp)[i];
        const int base = i * 4;
        const int row = base >> 5;
        const int d   = base & 31;
        float* qd = &sq[row * 33 + d];
        qd[0] = q4.x; qd[1] = q4.y; qd[2] = q4.z; qd[3] = q4.w;
    }
    __syncthreads();

    if (tid < NTOK) {
        float qreg[32];
#pragma unroll
        for (int d = 0; d < 32; d++) qreg[d] = sq[tid * 33 + d];

        const int qi = tid / 7, qj = tid - (tid / 7) * 7;
        const float* mrow = mask + (b & 63) * (NTOK * NTOK) + tid * NTOK;
        float* lrow = &slog[tid * NTOK];

        float mx = -1e30f;
        for (int j = 0; j < NTOK; j++) {
            float s = 0.f;
#pragma unroll
            for (int d = 0; d < 32; d++) s += qreg[d] * sk[j * 32 + d];  // broadcast LDS
            const int ki = j / 7, kj = j - ki * 7;
            const int idx = (qi - ki + 6) * 13 + (qj - kj + 6);
            s += bias_table[idx * NHEADS + h] + mrow[j];
            lrow[j] = s;
            mx = fmaxf(mx, s);
        }

        float sum = 0.f;
        for (int j = 0; j < NTOK; j++) {
            float e = __expf(lrow[j] - mx);
            lrow[j] = e;
            sum += e;
        }
        const float inv = 1.f / sum;

        float accv[32];
#pragma unroll
        for (int d = 0; d < 32; d++) accv[d] = 0.f;
        for (int j = 0; j < NTOK; j++) {
            const float w = lrow[j];
#pragma unroll
            for (int d = 0; d < 32; d++) accv[d] += w * sv[j * 32 + d];  // broadcast LDS
        }

        // write [B, 49, H*32] so proj GEMM reads contiguously
        float* op = g_att + (b * NTOK + tid) * EMB + h * HD;
#pragma unroll
        for (int d = 0; d < 32; d++) op[d] = accv[d] * inv;
    }
}

// ---------------------------------------------------------------------------
extern "C" void kernel_launch(void* const* d_in, const int* in_sizes, int n_in,
                              void* d_out, int out_size)
{
    const float* x          = (const float*)d_in[0];
    const float* mask       = (const float*)d_in[1];
    const float* qkv_w      = (const float*)d_in[2];
    const float* qkv_b      = (const float*)d_in[3];
    const float* proj_w     = (const float*)d_in[4];
    const float* proj_b     = (const float*)d_in[5];
    const float* bias_table = (const float*)d_in[6];
    float* out = (float*)d_out;

    gemm128<0><<<dim3(768 / 128, MROWS / 128), 256>>>(x, qkv_w, qkv_b, nullptr);
    attn_kernel<<<BQ * NHEADS, 64>>>(mask, bias_table);
    gemm128<1><<<dim3(EMB / 128, MROWS / 128), 256>>>(nullptr, proj_w, proj_b, out);
}

// round 5
// speedup vs baseline: 1.7874x; 1.7874x over previous
#include <cuda_runtime.h>
#include <cuda_bf16.h>
#include <cstdint>

#define BQ 4096
#define NTOK 49
#define EMB 256
#define NHEADS 8
#define HD 32
#define MROWS (BQ*NTOK)   // 200704 = 128*1568

// Scratch (device globals: allocation-free), 16B aligned for float4 access
__device__ __align__(16) float g_q[BQ*NHEADS*NTOK*HD];
__device__ __align__(16) float g_k[BQ*NHEADS*NTOK*HD];
__device__ __align__(16) float g_v[BQ*NHEADS*NTOK*HD];
__device__ __align__(16) float g_att[MROWS*EMB];

// ---------------------------------------------------------------------------
// PTX helpers: ldmatrix + bf16 mma.sync (supported on base sm_103 target)
// ---------------------------------------------------------------------------
__device__ __forceinline__ uint32_t smem_u32(const void* p) {
    uint32_t a;
    asm("{ .reg .u64 t; cvta.to.shared.u64 t, %1; cvt.u32.u64 %0, t; }"
        : "=r"(a) : "l"(p));
    return a;
}

__device__ __forceinline__ void ldm_x4(uint32_t& r0, uint32_t& r1,
                                       uint32_t& r2, uint32_t& r3, uint32_t addr) {
    asm volatile("ldmatrix.sync.aligned.m8n8.x4.shared.b16 {%0,%1,%2,%3}, [%4];"
                 : "=r"(r0), "=r"(r1), "=r"(r2), "=r"(r3) : "r"(addr));
}

__device__ __forceinline__ void mma_bf16(float* c, uint32_t a0, uint32_t a1,
                                         uint32_t a2, uint32_t a3,
                                         uint32_t b0, uint32_t b1) {
    asm volatile(
        "mma.sync.aligned.m16n8k16.row.col.f32.bf16.bf16.f32 "
        "{%0,%1,%2,%3}, {%4,%5,%6,%7}, {%8,%9}, {%0,%1,%2,%3};"
        : "+f"(c[0]), "+f"(c[1]), "+f"(c[2]), "+f"(c[3])
        : "r"(a0), "r"(a1), "r"(a2), "r"(a3), "r"(b0), "r"(b1));
}

__device__ __forceinline__ uint32_t pack_bf2(float a, float b) {
    __nv_bfloat162 v = __floats2bfloat162_rn(a, b);
    return *reinterpret_cast<uint32_t*>(&v);
}

// ---------------------------------------------------------------------------
// HMMA GEMM: C[m][n] = sum_k A[m][k]*W[n][k]  (+bias epilogue)
// 128x128 CTA tile, K in 8 chunks of 32, bf16 hi/lo split (3 mma passes).
// MODE 0: A=x, W=qkv_w, scatter q/k/v (q scaled).  MODE 1: A=g_att, W=proj_w.
// ---------------------------------------------------------------------------
#define SPAD 40   // bf16 row stride (32 data + 8 pad): conflict-free ldmatrix

__global__ void __launch_bounds__(256, 2)
__attribute__((unused)) dummy_decl();  // (nothing)

template<int MODE>
__global__ void __launch_bounds__(256, 2)
gemm_hmma(const float* __restrict__ A_in, const float* __restrict__ W,
          const float* __restrict__ bias, float* __restrict__ out)
{
    __shared__ __align__(16) __nv_bfloat16 s_ahi[128 * SPAD];
    __shared__ __align__(16) __nv_bfloat16 s_alo[128 * SPAD];
    __shared__ __align__(16) __nv_bfloat16 s_bhi[128 * SPAD];
    __shared__ __align__(16) __nv_bfloat16 s_blo[128 * SPAD];

    const float* __restrict__ A = (MODE == 0) ? A_in : (const float*)g_att;

    const int tid = threadIdx.x;
    const int wid = tid >> 5;
    const int lid = tid & 31;
    const int m0  = blockIdx.y * 128;
    const int n0b = blockIdx.x * 128;
    const int warpM = (wid >> 2) * 64;
    const int warpN = (wid & 3) * 32;

    const uint32_t uAhi = smem_u32(s_ahi);
    const uint32_t uAlo = smem_u32(s_alo);
    const uint32_t uBhi = smem_u32(s_bhi);
    const uint32_t uBlo = smem_u32(s_blo);

    // gmem load mapping: thread -> (row, 16 consecutive k)
    const int grow = tid >> 1;
    const int gkh  = (tid & 1) * 16;
    const float* Ag = A + (m0  + grow) * EMB + gkh;
    const float* Wg = W + (n0b + grow) * EMB + gkh;
    __nv_bfloat16* sa_h = s_ahi + grow * SPAD + gkh;
    __nv_bfloat16* sa_l = s_alo + grow * SPAD + gkh;
    __nv_bfloat16* sb_h = s_bhi + grow * SPAD + gkh;
    __nv_bfloat16* sb_l = s_blo + grow * SPAD + gkh;

    float acc[4][4][4];
#pragma unroll
    for (int i = 0; i < 4; i++)
#pragma unroll
        for (int j = 0; j < 4; j++)
#pragma unroll
            for (int r = 0; r < 4; r++) acc[i][j][r] = 0.f;

    // ldmatrix lane-address components (element offsets; x2 bytes at use)
    const int aRow = warpM + (lid & 15);          // + i*16
    const int aCol = (lid >> 4) << 3;             // + kk
    const int bRow = warpN + ((lid >> 4) << 3) + (lid & 7);  // + jj*16
    const int bCol = ((lid >> 3) & 1) << 3;       // + kk

    for (int c = 0; c < 8; ++c) {
        __syncthreads();   // protect smem from previous iteration's ldmatrix
        // ---- load + split 128x32 fp32 -> bf16 hi/lo tiles ----
        {
            const int ko = c * 32;
            float4 va0 = *(const float4*)(Ag + ko);
            float4 va1 = *(const float4*)(Ag + ko + 4);
            float4 va2 = *(const float4*)(Ag + ko + 8);
            float4 va3 = *(const float4*)(Ag + ko + 12);
            float4 vb0 = *(const float4*)(Wg + ko);
            float4 vb1 = *(const float4*)(Wg + ko + 4);
            float4 vb2 = *(const float4*)(Wg + ko + 8);
            float4 vb3 = *(const float4*)(Wg + ko + 12);

            float fa[16] = {va0.x,va0.y,va0.z,va0.w, va1.x,va1.y,va1.z,va1.w,
                            va2.x,va2.y,va2.z,va2.w, va3.x,va3.y,va3.z,va3.w};
            float fb[16] = {vb0.x,vb0.y,vb0.z,vb0.w, vb1.x,vb1.y,vb1.z,vb1.w,
                            vb2.x,vb2.y,vb2.z,vb2.w, vb3.x,vb3.y,vb3.z,vb3.w};

            uint32_t ah[8], al[8], bh[8], bl[8];
#pragma unroll
            for (int e = 0; e < 8; ++e) {
                float x0 = fa[2*e], x1 = fa[2*e+1];
                __nv_bfloat16 h0 = __float2bfloat16(x0);
                __nv_bfloat16 h1 = __float2bfloat16(x1);
                ah[e] = pack_bf2(x0, x1);  // rn pack of hi
                // recompute hi consistent with packed value
                __nv_bfloat162 hv = *reinterpret_cast<__nv_bfloat162*>(&ah[e]);
                al[e] = pack_bf2(x0 - __bfloat162float(hv.x),
                                 x1 - __bfloat162float(hv.y));
                (void)h0; (void)h1;

                float y0 = fb[2*e], y1 = fb[2*e+1];
                bh[e] = pack_bf2(y0, y1);
                __nv_bfloat162 bv = *reinterpret_cast<__nv_bfloat162*>(&bh[e]);
                bl[e] = pack_bf2(y0 - __bfloat162float(bv.x),
                                 y1 - __bfloat162float(bv.y));
            }
            ((uint4*)sa_h)[0] = make_uint4(ah[0],ah[1],ah[2],ah[3]);
            ((uint4*)sa_h)[1] = make_uint4(ah[4],ah[5],ah[6],ah[7]);
            ((uint4*)sa_l)[0] = make_uint4(al[0],al[1],al[2],al[3]);
            ((uint4*)sa_l)[1] = make_uint4(al[4],al[5],al[6],al[7]);
            ((uint4*)sb_h)[0] = make_uint4(bh[0],bh[1],bh[2],bh[3]);
            ((uint4*)sb_h)[1] = make_uint4(bh[4],bh[5],bh[6],bh[7]);
            ((uint4*)sb_l)[0] = make_uint4(bl[0],bl[1],bl[2],bl[3]);
            ((uint4*)sb_l)[1] = make_uint4(bl[4],bl[5],bl[6],bl[7]);
        }
        __syncthreads();

        // ---- 2 k16 steps ----
#pragma unroll
        for (int kk = 0; kk < 32; kk += 16) {
            uint32_t ahi[4][4], alo[4][4], bhi[4][2], blo[4][2];
#pragma unroll
            for (int i = 0; i < 4; ++i) {
                const uint32_t off = (uint32_t)(((aRow + i*16) * SPAD + kk + aCol) * 2);
                ldm_x4(ahi[i][0], ahi[i][1], ahi[i][2], ahi[i][3], uAhi + off);
                ldm_x4(alo[i][0], alo[i][1], alo[i][2], alo[i][3], uAlo + off);
            }
#pragma unroll
            for (int jj = 0; jj < 2; ++jj) {
                const uint32_t off = (uint32_t)(((bRow + jj*16) * SPAD + kk + bCol) * 2);
                uint32_t r0, r1, r2, r3;
                ldm_x4(r0, r1, r2, r3, uBhi + off);
                bhi[jj*2+0][0] = r0; bhi[jj*2+0][1] = r1;
                bhi[jj*2+1][0] = r2; bhi[jj*2+1][1] = r3;
                ldm_x4(r0, r1, r2, r3, uBlo + off);
                blo[jj*2+0][0] = r0; blo[jj*2+0][1] = r1;
                blo[jj*2+1][0] = r2; blo[jj*2+1][1] = r3;
            }
#pragma unroll
            for (int i = 0; i < 4; ++i)
#pragma unroll
                for (int j = 0; j < 4; ++j) {
                    mma_bf16(acc[i][j], ahi[i][0],ahi[i][1],ahi[i][2],ahi[i][3],
                             bhi[j][0], bhi[j][1]);
                    mma_bf16(acc[i][j], ahi[i][0],ahi[i][1],ahi[i][2],ahi[i][3],
                             blo[j][0], blo[j][1]);
                    mma_bf16(acc[i][j], alo[i][0],alo[i][1],alo[i][2],alo[i][3],
                             bhi[j][0], bhi[j][1]);
                }
        }
    }

    // ---- epilogue ----
#pragma unroll
    for (int i = 0; i < 4; ++i) {
#pragma unroll
        for (int j = 0; j < 4; ++j) {
            const int n = n0b + warpN + j * 8 + 2 * (lid & 3);
            const float b0 = bias[n], b1 = bias[n + 1];
#pragma unroll
            for (int half = 0; half < 2; ++half) {
                const int m = m0 + warpM + i * 16 + (lid >> 2) + half * 8;
                float2 o;
                o.x = acc[i][j][half*2+0] + b0;
                o.y = acc[i][j][half*2+1] + b1;
                if (MODE == 0) {
                    const int bb  = m / NTOK;
                    const int nn  = m - bb * NTOK;
                    const int sel = n >> 8;
                    const int h   = (n >> 5) & 7;
                    const int d   = n & 31;
                    if (sel == 0) { o.x *= 0.17677669529663687f; o.y *= 0.17677669529663687f; }
                    float* dst = (sel == 0 ? g_q : (sel == 1 ? g_k : g_v))
                                 + ((bb * NHEADS + h) * NTOK + nn) * HD + d;
                    *(float2*)dst = o;
                } else {
                    *(float2*)(out + m * EMB + n) = o;
                }
            }
        }
    }
}

// ---------------------------------------------------------------------------
// Attention: one block per (b,h); float4-vectorized LDS
// ---------------------------------------------------------------------------
__global__ void __launch_bounds__(64)
attn_kernel(const float* __restrict__ mask, const float* __restrict__ bias_table)
{
    __shared__ __align__(16) float sk[NTOK * 32];
    __shared__ __align__(16) float sv[NTOK * 32];
    __shared__ float slog[NTOK * 49];

    const int tid = threadIdx.x;
    const int bh  = blockIdx.x;
    const int b   = bh >> 3;
    const int h   = bh & 7;

    const float* kp = g_k + bh * (NTOK * HD);
    const float* vp = g_v + bh * (NTOK * HD);

    for (int i = tid; i < (NTOK * HD) / 4; i += 64) {
        ((float4*)sk)[i] = ((const float4*)kp)[i];
        ((float4*)sv)[i] = ((const float4*)vp)[i];
    }
    __syncthreads();

    if (tid < NTOK) {
        float4 qv[8];
        const float4* qp4 = (const float4*)(g_q + bh * (NTOK * HD) + tid * HD);
#pragma unroll
        for (int i = 0; i < 8; ++i) qv[i] = qp4[i];

        const int qi = tid / 7, qj = tid - (tid / 7) * 7;
        const float* mrow = mask + (b & 63) * (NTOK * NTOK) + tid * NTOK;
        float* lrow = &slog[tid * 49];

        float mx = -1e30f;
        for (int j = 0; j < NTOK; ++j) {
            const float4* kr = (const float4*)(sk + j * 32);
            float s = 0.f;
#pragma unroll
            for (int i = 0; i < 8; ++i) {
                const float4 kk = kr[i];
                s += qv[i].x * kk.x + qv[i].y * kk.y + qv[i].z * kk.z + qv[i].w * kk.w;
            }
            const int ki = j / 7, kj = j - ki * 7;
            s += bias_table[((qi - ki + 6) * 13 + (qj - kj + 6)) * NHEADS + h] + mrow[j];
            lrow[j] = s;
            mx = fmaxf(mx, s);
        }

        float sum = 0.f;
        for (int j = 0; j < NTOK; ++j) {
            const float e = __expf(lrow[j] - mx);
            lrow[j] = e;
            sum += e;
        }
        const float inv = 1.f / sum;

        float4 accv[8];
#pragma unroll
        for (int i = 0; i < 8; ++i) accv[i] = make_float4(0.f, 0.f, 0.f, 0.f);
        for (int j = 0; j < NTOK; ++j) {
            const float w = lrow[j];
            const float4* vr = (const float4*)(sv + j * 32);
#pragma unroll
            for (int i = 0; i < 8; ++i) {
                const float4 vv = vr[i];
                accv[i].x += w * vv.x; accv[i].y += w * vv.y;
                accv[i].z += w * vv.z; accv[i].w += w * vv.w;
            }
        }

        float* op = g_att + (b * NTOK + tid) * EMB + h * HD;
#pragma unroll
        for (int i = 0; i < 8; ++i) {
            float4 o = accv[i];
            o.x *= inv; o.y *= inv; o.z *= inv; o.w *= inv;
            ((float4*)op)[i] = o;
        }
    }
}

// ---------------------------------------------------------------------------
extern "C" void kernel_launch(void* const* d_in, const int* in_sizes, int n_in,
                              void* d_out, int out_size)
{
    const float* x          = (const float*)d_in[0];
    const float* mask       = (const float*)d_in[1];
    const float* qkv_w      = (const float*)d_in[2];
    const float* qkv_b      = (const float*)d_in[3];
    const float* proj_w     = (const float*)d_in[4];
    const float* proj_b     = (const float*)d_in[5];
    const float* bias_table = (const float*)d_in[6];
    float* out = (float*)d_out;

    gemm_hmma<0><<<dim3(768 / 128, MROWS / 128), 256>>>(x, qkv_w, qkv_b, nullptr);
    attn_kernel<<<BQ * NHEADS, 64>>>(mask, bias_table);
    gemm_hmma<1><<<dim3(EMB / 128, MROWS / 128), 256>>>(nullptr, proj_w, proj_b, out);
}